// round 14
// baseline (speedup 1.0000x reference)
#include <cuda_runtime.h>
#include <cuda_bf16.h>
#include <math.h>

// Problem dims (fixed by the dataset)
#define Nn 64
#define Cc 8
#define Tt 300
#define Vv 17
#define Mm 12
#define SLICES (Nn*Cc*Tt)          // 153600 (n,c,t) slices of V*M=204 floats
#define EPSF 1e-6f
#define TAUF 0.35f

#define NCHUNK 10                  // T split into 10 chunks of 30
#define CH 30                      // t per chunk
#define SL 48                      // slices per block in fused kernel (48 | 2400)

// Scratch (device globals — no allocation allowed)
__device__ float g_A[Nn*Mm*Mm];               // per-sample 12x12 adjacency
__device__ float g_part[Nn*NCHUNK*48];        // partials: 12 s + 36 pos per (n,chunk)

// packed f32x2 add (bit-identical to scalar FADD.rn)
__device__ __forceinline__ float4 f4add(float4 a, float4 b) {
    union { float4 f; unsigned long long u[2]; } A, B, O;
    A.f = a; B.f = b;
    asm("add.rn.f32x2 %0, %1, %2;" : "=l"(O.u[0]) : "l"(A.u[0]), "l"(B.u[0]));
    asm("add.rn.f32x2 %0, %1, %2;" : "=l"(O.u[1]) : "l"(A.u[1]), "l"(B.u[1]));
    return O.f;
}

// ---------------------------------------------------------------------------
// Kernel 1: partial reductions. grid = 64*10 = 640 blocks, 256 threads.
// Triggers dependent launch immediately (writes g_part; consumers wait on
// full grid completion via griddepcontrol.wait, so early trigger is safe).
// ---------------------------------------------------------------------------
__global__ __launch_bounds__(256) void stats1_kernel(const float* __restrict__ x)
{
    cudaTriggerProgrammaticLaunchCompletion();

    const int b   = blockIdx.x;
    const int n   = b / NCHUNK, ch = b % NCHUNK;
    const int tid = threadIdx.x;
    const float* xn = x + (size_t)n * Cc * Tt * Vv * Mm;

    __shared__ float4 sred4[256];
    __shared__ float4 posq[3][CH][6];

    // ---- s partial loads: 1530 float4 = 6*255, 6 per thread (same m-phase)
    {
        const float4* slab = (const float4*)(xn + 3 * Tt * Vv * Mm + ch * CH * 204);
        float4 acc = make_float4(0.f, 0.f, 0.f, 0.f);
        if (tid < 255) {
            float4 q0 = slab[tid];
            float4 q1 = slab[tid + 255];
            float4 q2 = slab[tid + 510];
            float4 q3 = slab[tid + 765];
            float4 q4 = slab[tid + 1020];
            float4 q5 = slab[tid + 1275];
            acc = f4add(f4add(f4add(q0, q1), f4add(q2, q3)), f4add(q4, q5));
        }
        sred4[tid] = acc;
    }

    // ---- pos loads: 180 threads, 3 float4 each (one per d)
    if (tid < CH * 6) {
        const int tl = tid / 6, q = tid % 6;
#pragma unroll
        for (int d = 0; d < 3; d++) {
            const float4* x4n = (const float4*)(xn + (size_t)d * Tt * Vv * Mm);
            posq[d][tl][q] = x4n[(ch * CH + tl) * 51 + 33 + q];
        }
    }
    __syncthreads();

    // ---- s reduce stage 1: 255 -> 51 (51 % 3 == 0 keeps phases)
    if (tid < 51) {
        float4 a = f4add(sred4[tid], sred4[tid + 51]);
        float4 c = f4add(sred4[tid + 102], sred4[tid + 153]);
        sred4[tid] = f4add(f4add(a, c), sred4[tid + 204]);
    }
    __syncthreads();

    if (tid < 12) {
        const int p = tid / 4, c = tid % 4;       // m = 4p + c
        float t = 0.f;
#pragma unroll
        for (int j = 0; j < 17; j++)
            t += ((const float*)&sred4[p + 3 * j])[c];
        g_part[b * 48 + tid] = t;
    } else if (tid < 48) {
        const int d = (tid - 12) / 12, m = (tid - 12) % 12;
        const int q1 = m / 4, c = m % 4;          // joint 12 = float m+12 -> q1+3
        const float* pf = (const float*)&posq[d][0][0];
        float t = 0.f;
#pragma unroll
        for (int tl = 0; tl < CH; tl++)
            t += pf[(tl * 6 + q1) * 4 + c] + pf[(tl * 6 + q1 + 3) * 4 + c];
        g_part[b * 48 + tid] = t;
    }
}

// ---------------------------------------------------------------------------
// Kernel 2: reduce partials + build A. grid = 64 blocks, 256 threads.
// PDL: triggers its dependent (fused) at entry, then waits for stats1.
// ---------------------------------------------------------------------------
__global__ __launch_bounds__(256) void graph_kernel(const float* __restrict__ alpha_logits)
{
    cudaTriggerProgrammaticLaunchCompletion();
    cudaGridDependencySynchronize();            // g_part ready after this

    const int n = blockIdx.x, tid = threadIdx.x;
    __shared__ float red2[5][48];
    __shared__ float s[12], pos[3][12], p[12], alpha[4], wsh;

    if (tid < 240) {
        const int g = tid / 48, j = tid % 48;
        red2[g][j] = g_part[(n * NCHUNK + g * 2) * 48 + j]
                   + g_part[(n * NCHUNK + g * 2 + 1) * 48 + j];
    }
    if (tid == 255) {
        float mx = alpha_logits[0];
        for (int k = 1; k < 4; k++) mx = fmaxf(mx, alpha_logits[k]);
        float e[4], se = 0.f;
        for (int k = 0; k < 4; k++) { e[k] = expf(alpha_logits[k] - mx); se += e[k]; }
        for (int k = 0; k < 4; k++) alpha[k] = e[k] / se;
    }
    __syncthreads();

    if (tid < 48) {
        float t = red2[0][tid] + red2[1][tid] + red2[2][tid]
                + red2[3][tid] + red2[4][tid];
        if (tid < 12) s[tid] = t * (1.0f / (Tt * Vv));
        else {
            const int d = (tid - 12) / 12, m = (tid - 12) % 12;
            pos[d][m] = t * (0.5f / Tt);
        }
    }
    __syncthreads();

    if (tid == 0) {
        float smax = -1e30f;
        for (int m = 0; m < 12; m++) smax = fmaxf(smax, s[m] * (1.0f / TAUF));
        float ps = 0.f;
        for (int m = 0; m < 12; m++) { p[m] = expf(s[m] * (1.0f / TAUF) - smax); ps += p[m]; }
        float pmax = 0.f;
        for (int m = 0; m < 12; m++) { p[m] /= ps; pmax = fmaxf(pmax, p[m]); }

        float w = (pmax - 1.0f / 12.0f) / (1.0f - 1.0f / 12.0f + EPSF);
        wsh = fminf(fmaxf(w, 0.0f), 1.0f);
    }
    __syncthreads();

    if (tid < 12) {
        const int i = tid;
        float dist[12];
        for (int j = 0; j < 12; j++) {
            float dx = pos[0][i] - pos[0][j];
            float dy = pos[1][i] - pos[1][j];
            float dz = pos[2][i] - pos[2][j];
            dist[j] = dx * dx + dy * dy + dz * dz;   // monotone in euclid
        }
        // 5-NN selection order; ties -> lowest index (matches jax top_k)
        int rank[12];
        bool used[12];
        for (int j = 0; j < 12; j++) { rank[j] = 9; used[j] = false; }
        for (int r = 0; r < 5; r++) {
            float best = 3.4e38f; int bj = 0;
            for (int j = 0; j < 12; j++)
                if (!used[j] && dist[j] < best) { best = dist[j]; bj = j; }
            used[bj] = true; rank[bj] = r;
        }
        // sym_norm(A_k) = A_k / (k+1+eps): row sums are exactly k+1
        float invk[4];
        for (int kidx = 0; kidx < 4; kidx++) {
            float ds = rsqrtf((float)(kidx + 3) + EPSF);
            invk[kidx] = alpha[kidx] * ds * ds;
        }
        const float diagsum = invk[0] + invk[1] + invk[2] + invk[3];
        float rankw[5];
        rankw[0] = diagsum;
        rankw[1] = diagsum;
        rankw[2] = invk[1] + invk[2] + invk[3];
        rankw[3] = invk[2] + invk[3];
        rankw[4] = invk[3];

        const float w = wsh;
        const float disb_i = rsqrtf(12.0f * p[i] + 2.0f + EPSF);
        float* Arow = g_A + (n * 144 + i * 12);
        for (int j = 0; j < 12; j++) {
            float aknn = (rank[j] < 5 ? rankw[rank[j]] : 0.0f)
                       + (i == j ? diagsum : 0.0f);
            float disb_j = rsqrtf(12.0f * p[j] + 2.0f + EPSF);
            float aball = disb_i * disb_j * (p[i] + p[j] + (i == j ? 1.0f : 0.0f));
            Arow[j] = w * aball + (1.0f - w) * aknn;
        }
    }
}

// ---------------------------------------------------------------------------
// Kernel 3 (fused): 48 slices per block, 3200 blocks.
// PDL preamble: batch streaming loads + root staging (x-only) BEFORE the
// grid-dependency wait; g_A is read only after the wait.
// ---------------------------------------------------------------------------
__global__ __launch_bounds__(256) void fused_kernel(
    const float* __restrict__ x, float* __restrict__ out,
    const float* __restrict__ lambda_fuse, const float* __restrict__ tag_gate)
{
    const int slice0 = blockIdx.x * SL;         // 48 | 2400 -> block within one n
    const int n      = slice0 / (Cc * Tt);
    const int tid    = threadIdx.x;

    __shared__ float A_s[144];
    __shared__ float r_s[SL][12];
    __shared__ float delta_s[SL][12];           // 48B rows, float4-aligned
    __shared__ float coef_s;

    const float4* x4base = (const float4*)x + (size_t)slice0 * 51;
    const bool extra = tid < 144;

    // ---- PDL preamble: 2448 float4 batch (9*256 + 144), 10-deep MLP
    float4 xv[10];
#pragma unroll
    for (int it = 0; it < 9; ++it)
        xv[it] = __ldcs(&x4base[tid + it * 256]);
    if (extra)
        xv[9] = __ldcs(&x4base[tid + 9 * 256]);

    // Phase 1: root staging (x only; overlaps predecessor kernels)
    if (tid < SL * 3) {
        const int sidx = tid / 3, q = tid - sidx * 3;
        const float4 a  = x4base[sidx * 51 + 33 + q];
        const float4 bq = x4base[sidx * 51 + 36 + q];
        float4 r;
        r.x = 0.5f * (a.x + bq.x);
        r.y = 0.5f * (a.y + bq.y);
        r.z = 0.5f * (a.z + bq.z);
        r.w = 0.5f * (a.w + bq.w);
        *(float4*)&r_s[sidx][q * 4] = r;
    }
    if (tid == 0) coef_s = tanhf(tag_gate[0]) * lambda_fuse[0];

    // ---- wait for graph_kernel completion (g_A visible after this)
    cudaGridDependencySynchronize();

    if (tid < 144) A_s[tid] = g_A[n * 144 + tid];
    __syncthreads();

    // Phase 2: 576 delta items
    for (int it = tid; it < SL * 12; it += 256) {
        const int sidx = it / 12, m = it - sidx * 12;
        const float4 a0 = *(const float4*)&A_s[m * 12 + 0];
        const float4 a1 = *(const float4*)&A_s[m * 12 + 4];
        const float4 a2 = *(const float4*)&A_s[m * 12 + 8];
        const float4 r0 = *(const float4*)&r_s[sidx][0];
        const float4 r1 = *(const float4*)&r_s[sidx][4];
        const float4 r2 = *(const float4*)&r_s[sidx][8];
        float agg = a0.x * r0.x + a0.y * r0.y + a0.z * r0.z + a0.w * r0.w
                  + a1.x * r1.x + a1.y * r1.y + a1.z * r1.z + a1.w * r1.w
                  + a2.x * r2.x + a2.y * r2.y + a2.z * r2.z + a2.w * r2.w;
        delta_s[sidx][m] = coef_s * (agg - r_s[sidx][m]);
    }
    __syncthreads();

    // Phase 3: stores (xv already resident / arriving)
    float4* o4 = (float4*)out + (size_t)slice0 * 51;
    const char* dmem = (const char*)delta_s;

    int r    = tid % 51;
    int rm3  = r % 3;
    int doff = (tid / 51) * 48;

#pragma unroll
    for (int it = 0; it < 9; ++it) {
        const float4 d = *(const float4*)(dmem + (doff + rm3 * 16));
        __stcs(&o4[tid + it * 256], f4add(xv[it], d));
        doff += 240;
        rm3 = (rm3 == 2) ? 0 : rm3 + 1;
        r += 1;
        if (r == 51) { r = 0; doff += 48; }
    }
    if (extra) {
        const float4 d = *(const float4*)(dmem + (doff + rm3 * 16));
        __stcs(&o4[tid + 9 * 256], f4add(xv[9], d));
    }
}

// ---------------------------------------------------------------------------
extern "C" void kernel_launch(void* const* d_in, const int* in_sizes, int n_in,
                              void* d_out, int out_size)
{
    const float* x            = (const float*)d_in[0];
    const float* alpha_logits = (const float*)d_in[1];
    const float* lambda_fuse  = (const float*)d_in[2];
    const float* tag_gate     = (const float*)d_in[3];
    float* out = (float*)d_out;

    // k1: normal launch
    stats1_kernel<<<Nn * NCHUNK, 256>>>(x);

    // k2, k3: programmatic dependent launches (overlap with predecessor)
    cudaLaunchAttribute attr[1];
    attr[0].id = cudaLaunchAttributeProgrammaticStreamSerialization;
    attr[0].val.programmaticStreamSerializationAllowed = 1;

    {
        cudaLaunchConfig_t cfg = {};
        cfg.gridDim = dim3(Nn, 1, 1);
        cfg.blockDim = dim3(256, 1, 1);
        cfg.dynamicSmemBytes = 0;
        cfg.stream = 0;
        cfg.attrs = attr;
        cfg.numAttrs = 1;
        cudaLaunchKernelEx(&cfg, graph_kernel, alpha_logits);
    }
    {
        cudaLaunchConfig_t cfg = {};
        cfg.gridDim = dim3(SLICES / SL, 1, 1);
        cfg.blockDim = dim3(256, 1, 1);
        cfg.dynamicSmemBytes = 0;
        cfg.stream = 0;
        cfg.attrs = attr;
        cfg.numAttrs = 1;
        cudaLaunchKernelEx(&cfg, fused_kernel, x, out, lambda_fuse, tag_gate);
    }
}